// round 4
// baseline (speedup 1.0000x reference)
#include <cuda_runtime.h>
#include <cuda_fp16.h>
#include <cstdint>

// ============================================================================
// C[8192,1024] = A[8192,4096] @ B[1024,4096]^T   (fp32 in/out)
//
// Base sm_103 target (no tcgen05). Single-pass fp16 mma.sync.m16n8k16
// (rel_err ~2.9e-4, validated R3). R4: warp tile 64x64 (4 warps/CTA,
// 2 CTAs/SM) for 2x compute density per LDSM and 32-deep independent
// MMA chains per warp.
// ============================================================================

static constexpr int M_TOTAL = 8192;
static constexpr int K_DIM   = 4096;
static constexpr int N_TOTAL = 1024;

static constexpr int BM = 128;
static constexpr int BN = 128;
static constexpr int BK = 64;          // 64 fp16 = 128 B per smem row
static constexpr int STAGES = 3;
static constexpr int NK = K_DIM / BK;  // 64

static constexpr int TILE_BYTES  = BM * BK * 2;       // 16384 per array
static constexpr int STAGE_BYTES = 2 * TILE_BYTES;    // 32768 (A + B)
static constexpr int SMEM_TOTAL  = STAGES * STAGE_BYTES; // 98304 -> 2 CTAs/SM

// --------------------------------------------------------------------------
// Static scratch: fp16 copies of A and B
// --------------------------------------------------------------------------
__device__ __half g_Ah[(size_t)M_TOTAL * K_DIM];
__device__ __half g_Bh[(size_t)N_TOTAL * K_DIM];

// --------------------------------------------------------------------------
// Convert kernel: fp32 -> fp16 (vectorized 4-wide)
// --------------------------------------------------------------------------
__global__ void __launch_bounds__(256)
cvt_kernel(const float4* __restrict__ src, uint2* __restrict__ dst, int n4) {
    int i = blockIdx.x * blockDim.x + threadIdx.x;
    if (i >= n4) return;
    float4 v = src[i];
    __half2 lo = __floats2half2_rn(v.x, v.y);
    __half2 hi = __floats2half2_rn(v.z, v.w);
    dst[i] = make_uint2(*reinterpret_cast<uint32_t*>(&lo), *reinterpret_cast<uint32_t*>(&hi));
}

// --------------------------------------------------------------------------
// PTX helpers (base-target legal)
// --------------------------------------------------------------------------
__device__ __forceinline__ void cp_async16(uint32_t saddr, const void* gptr) {
    asm volatile("cp.async.cg.shared.global [%0], [%1], 16;"
                 :: "r"(saddr), "l"(__cvta_generic_to_global(gptr)) : "memory");
}

#define CP_COMMIT() asm volatile("cp.async.commit_group;" ::: "memory")
#define CP_WAIT(N)  asm volatile("cp.async.wait_group %0;" :: "n"(N) : "memory")

#define LDSM_X4(R, addr)                                                     \
    asm volatile("ldmatrix.sync.aligned.m8n8.x4.shared.b16 {%0,%1,%2,%3}, [%4];" \
                 : "=r"((R)[0]), "=r"((R)[1]), "=r"((R)[2]), "=r"((R)[3])    \
                 : "r"(addr))

#define MMA_F16(C, A, B0, B1)                                                \
    asm volatile("mma.sync.aligned.m16n8k16.row.col.f32.f16.f16.f32 "        \
                 "{%0,%1,%2,%3}, {%4,%5,%6,%7}, {%8,%9}, {%0,%1,%2,%3};"     \
                 : "+f"((C)[0]), "+f"((C)[1]), "+f"((C)[2]), "+f"((C)[3])    \
                 : "r"((A)[0]), "r"((A)[1]), "r"((A)[2]), "r"((A)[3]),       \
                   "r"(B0), "r"(B1))

// smem tile: row-major [128 rows][64 fp16] = 128 B/row, 16B chunks
// XOR-swizzled by (row & 7): conflict-free cp.async + ldmatrix.
__device__ __forceinline__ uint32_t swz(int row, int col_bytes) {
    return (uint32_t)(row * 128 + (col_bytes ^ ((row & 7) * 16)));
}

// --------------------------------------------------------------------------
// GEMM kernel: CTA 128x128x64, 4 warps of 64x64, 3-stage cp.async, 2 CTAs/SM
// --------------------------------------------------------------------------
__global__ void __launch_bounds__(128, 2)
gemm_f16_kernel(float* __restrict__ C) {
    extern __shared__ uint8_t smem[];
    const uint32_t sbase = (uint32_t)__cvta_generic_to_shared(smem);

    const int tid  = threadIdx.x;
    const int lane = tid & 31;
    const int wid  = tid >> 5;          // 0..3
    const int wm   = (wid & 1) * 64;    // warp M offset
    const int wn   = (wid >> 1) * 64;   // warp N offset

    const int m0 = blockIdx.y * BM;
    const int n0 = blockIdx.x * BN;

    // ---- stage loader: 1024 x 16B chunks per array, 128 threads x 8 ----
    auto load_stage = [&](int s, int kt) {
        const uint32_t st = sbase + s * STAGE_BYTES;
        const int kbase = kt * BK;
        #pragma unroll
        for (int i = 0; i < 8; i++) {
            const int idx = tid + i * 128;
            const int row = idx >> 3;
            const int ch  = idx & 7;
            const uint32_t soff = swz(row, ch * 16);
            cp_async16(st +              soff, &g_Ah[(size_t)(m0 + row) * K_DIM + kbase + ch * 8]);
            cp_async16(st + TILE_BYTES + soff, &g_Bh[(size_t)(n0 + row) * K_DIM + kbase + ch * 8]);
        }
    };

    // ---- ldmatrix address components ----
    int a_row[4], a_xor[4];
    #pragma unroll
    for (int m = 0; m < 4; m++) {
        const int r = wm + m * 16 + (lane & 15);
        a_row[m] = r * 128;
        a_xor[m] = (r & 7) * 16;
    }
    const int a_colb = (lane >> 4) * 16;
    int b_row[4], b_xor[4];
    #pragma unroll
    for (int p = 0; p < 4; p++) {
        const int r = wn + p * 16 + (lane & 7) + ((lane >> 4) << 3);
        b_row[p] = r * 128;
        b_xor[p] = (r & 7) * 16;
    }
    const int b_colb = ((lane >> 3) & 1) * 16;

    float acc[4][8][4];
    #pragma unroll
    for (int m = 0; m < 4; m++)
        #pragma unroll
        for (int n = 0; n < 8; n++)
            #pragma unroll
            for (int q = 0; q < 4; q++) acc[m][n][q] = 0.f;

    // ---- prologue: 2 stages in flight ----
    load_stage(0, 0); CP_COMMIT();
    load_stage(1, 1); CP_COMMIT();

    // ---- mainloop: ONE barrier per k-iter ----
    for (int kt = 0; kt < NK; kt++) {
        if (kt < NK - 1) { CP_WAIT(1); } else { CP_WAIT(0); }
        __syncthreads();   // stage kt ready AND all warps done with stage kt-1
        if (kt + 2 < NK) {
            load_stage((kt + 2) % STAGES, kt + 2);   // overwrites stage kt-1
            CP_COMMIT();
        }

        const uint32_t st = sbase + (kt % STAGES) * STAGE_BYTES;
        #pragma unroll
        for (int ks = 0; ks < 4; ks++) {        // four k16 steps in BK=64
            const int kb = ks * 32;             // k byte offset
            uint32_t a[4][4];
            #pragma unroll
            for (int m = 0; m < 4; m++)
                LDSM_X4(a[m], st + a_row[m] + ((kb + a_colb) ^ a_xor[m]));
            uint32_t b[4][4];
            #pragma unroll
            for (int p = 0; p < 4; p++)
                LDSM_X4(b[p], st + TILE_BYTES + b_row[p] + ((kb + b_colb) ^ b_xor[p]));
            #pragma unroll
            for (int m = 0; m < 4; m++)
                #pragma unroll
                for (int p = 0; p < 4; p++)
                    #pragma unroll
                    for (int q = 0; q < 2; q++)
                        MMA_F16(acc[m][2 * p + q], a[m], b[p][2 * q], b[p][2 * q + 1]);
        }
    }

    // ---- epilogue: direct STG.64 ----
    #pragma unroll
    for (int m = 0; m < 4; m++) {
        const int r0 = m0 + wm + m * 16 + (lane >> 2);
        #pragma unroll
        for (int n = 0; n < 8; n++) {
            const int col = n0 + wn + n * 8 + (lane & 3) * 2;
            float2* p0 = reinterpret_cast<float2*>(&C[(size_t)r0 * N_TOTAL + col]);
            float2* p1 = reinterpret_cast<float2*>(&C[(size_t)(r0 + 8) * N_TOTAL + col]);
            *p0 = make_float2(acc[m][n][0], acc[m][n][1]);
            *p1 = make_float2(acc[m][n][2], acc[m][n][3]);
        }
    }
}

// --------------------------------------------------------------------------
// Launch
// --------------------------------------------------------------------------
extern "C" void kernel_launch(void* const* d_in, const int* in_sizes, int n_in,
                              void* d_out, int out_size) {
    const float* A = (const float*)d_in[0];   // [8192, 4096]
    const float* B = (const float*)d_in[1];   // [1024, 4096]
    float* C = (float*)d_out;                 // [8192, 1024]

    __half *aH, *bH;
    cudaGetSymbolAddress((void**)&aH, g_Ah);
    cudaGetSymbolAddress((void**)&bH, g_Bh);

    const int nA4 = (M_TOTAL * K_DIM) / 4;
    const int nB4 = (N_TOTAL * K_DIM) / 4;
    cvt_kernel<<<(nA4 + 255) / 256, 256>>>((const float4*)A, (uint2*)aH, nA4);
    cvt_kernel<<<(nB4 + 255) / 256, 256>>>((const float4*)B, (uint2*)bH, nB4);

    static bool attr_set = false;
    if (!attr_set) {
        cudaFuncSetAttribute(gemm_f16_kernel,
                             cudaFuncAttributeMaxDynamicSharedMemorySize, SMEM_TOTAL);
        attr_set = true;
    }
    dim3 grid(N_TOTAL / BN, M_TOTAL / BM);    // (8, 64): n-fastest -> A tile L2 reuse
    gemm_f16_kernel<<<grid, 128, SMEM_TOTAL>>>(C);
}